// round 2
// baseline (speedup 1.0000x reference)
#include <cuda_runtime.h>
#include <cuda_bf16.h>

// Problem: B=8, H=512, W=512
// Inputs (metadata order):
//   0: t        (8,1,1,1)     float32
//   1: I0       (8,512,512,3) float32
//   2: I1       (8,512,512,3) float32
//   3: interp   (8,512,512,5) float32
//   4: Fhat_t0  (8,512,512,2) float32
//   5: Fhat_t1  (8,512,512,2) float32
// Output: It (8,512,512,3) float32

#define W_DIM 512
#define H_DIM 512
#define B_DIM 8
#define HW (H_DIM * W_DIM)
#define NPIX (B_DIM * HW)
#define PIX_PER_THREAD 4

__device__ __forceinline__ float3 bilerp3(const float* __restrict__ img,
                                          float x, float y) {
    float x0f = floorf(x);
    float y0f = floorf(y);
    float wx = x - x0f;
    float wy = y - y0f;
    int x0 = min(max((int)x0f, 0), W_DIM - 1);
    int x1 = min(max((int)x0f + 1, 0), W_DIM - 1);
    int y0 = min(max((int)y0f, 0), H_DIM - 1);
    int y1 = min(max((int)y0f + 1, 0), H_DIM - 1);

    float wa = (1.f - wx) * (1.f - wy);
    float wb = (1.f - wx) * wy;
    float wc = wx * (1.f - wy);
    float wd = wx * wy;

    const float* r0 = img + y0 * (W_DIM * 3);
    const float* r1 = img + y1 * (W_DIM * 3);
    int a = x0 * 3;
    int c = x1 * 3;

    // Issue all 12 loads up front for MLP; FMAs consume afterwards.
    float a0 = __ldg(r0 + a + 0), a1 = __ldg(r0 + a + 1), a2 = __ldg(r0 + a + 2);
    float b0 = __ldg(r1 + a + 0), b1 = __ldg(r1 + a + 1), b2 = __ldg(r1 + a + 2);
    float c0 = __ldg(r0 + c + 0), c1 = __ldg(r0 + c + 1), c2 = __ldg(r0 + c + 2);
    float d0 = __ldg(r1 + c + 0), d1 = __ldg(r1 + c + 1), d2 = __ldg(r1 + c + 2);

    float3 o;
    o.x = a0 * wa + b0 * wb + c0 * wc + d0 * wd;
    o.y = a1 * wa + b1 * wb + c1 * wc + d1 * wd;
    o.z = a2 * wa + b2 * wb + c2 * wc + d2 * wd;
    return o;
}

__global__ void __launch_bounds__(256)
imagecomp_kernel(const float* __restrict__ t,
                 const float* __restrict__ I0,
                 const float* __restrict__ I1,
                 const float* __restrict__ interp,
                 const float* __restrict__ F0,
                 const float* __restrict__ F1,
                 float* __restrict__ out) {
    int gid = blockIdx.x * blockDim.x + threadIdx.x;
    int base = gid * PIX_PER_THREAD;
    if (base >= NPIX) return;

    int b = base >> 18;           // / (512*512)
    int p = base & (HW - 1);
    int yi = p >> 9;
    int xi = p & (W_DIM - 1);     // 4 consecutive pixels: same b, same row

    // ---- vectorized streaming loads ----
    union { float4 v[5]; float a[20]; } ip;   // interp: 4 px x 5 ch
    {
        const float4* ip4 = (const float4*)(interp + (size_t)base * 5);
        #pragma unroll
        for (int i = 0; i < 5; i++) ip.v[i] = __ldg(ip4 + i);
    }
    union { float4 v[2]; float a[8]; } f0v, f1v;  // flows: 4 px x 2
    {
        const float4* f04 = (const float4*)(F0 + (size_t)base * 2);
        const float4* f14 = (const float4*)(F1 + (size_t)base * 2);
        f0v.v[0] = __ldg(f04 + 0); f0v.v[1] = __ldg(f04 + 1);
        f1v.v[0] = __ldg(f14 + 0); f1v.v[1] = __ldg(f14 + 1);
    }

    float tb = __ldg(t + b);
    float one_m_tb = 1.f - tb;

    const float* img0 = I0 + (size_t)b * (HW * 3);
    const float* img1 = I1 + (size_t)b * (HW * 3);
    float gy = (float)yi;

    union { float4 v[3]; float a[12]; } res;  // output: 4 px x 3

    #pragma unroll
    for (int j = 0; j < PIX_PER_THREAD; j++) {
        float c0 = ip.a[5 * j + 0];
        float c1 = ip.a[5 * j + 1];
        float c2 = ip.a[5 * j + 2];
        float c3 = ip.a[5 * j + 3];
        float c4 = ip.a[5 * j + 4];

        float ft0x = c0 + f0v.a[2 * j + 0];
        float ft0y = c1 + f0v.a[2 * j + 1];
        float ft1x = c2 + f1v.a[2 * j + 0];
        float ft1y = c3 + f1v.a[2 * j + 1];

        float vt0 = 1.f / (1.f + __expf(-c4));
        float vt1 = 1.f - vt0;
        float w0 = one_m_tb * vt0;
        float w1 = tb * vt1;
        float inv_den = __fdividef(1.f, w0 + w1 + 1e-12f);

        float gx = (float)(xi + j);
        float3 g0 = bilerp3(img0, gx + ft0x, gy + ft0y);
        float3 g1 = bilerp3(img1, gx + ft1x, gy + ft1y);

        res.a[3 * j + 0] = (w0 * g0.x + w1 * g1.x) * inv_den;
        res.a[3 * j + 1] = (w0 * g0.y + w1 * g1.y) * inv_den;
        res.a[3 * j + 2] = (w0 * g0.z + w1 * g1.z) * inv_den;
    }

    float4* o4 = (float4*)(out + (size_t)base * 3);
    o4[0] = res.v[0];
    o4[1] = res.v[1];
    o4[2] = res.v[2];
}

extern "C" void kernel_launch(void* const* d_in, const int* in_sizes, int n_in,
                              void* d_out, int out_size) {
    const float* t      = (const float*)d_in[0];
    const float* I0     = (const float*)d_in[1];
    const float* I1     = (const float*)d_in[2];
    const float* interp = (const float*)d_in[3];
    const float* F0     = (const float*)d_in[4];
    const float* F1     = (const float*)d_in[5];
    float* out = (float*)d_out;

    int threads = 256;
    int nthreads_total = NPIX / PIX_PER_THREAD;
    int blocks = (nthreads_total + threads - 1) / threads;
    imagecomp_kernel<<<blocks, threads>>>(t, I0, I1, interp, F0, F1, out);
}

// round 3
// speedup vs baseline: 1.5062x; 1.5062x over previous
#include <cuda_runtime.h>
#include <cuda_fp16.h>

// Problem: B=8, H=512, W=512
// Inputs: t(8,1,1,1) I0,I1(8,512,512,3) interp(8,512,512,5) Fhat_t0/t1(8,512,512,2)
// Output: It (8,512,512,3) float32

#define W_DIM 512
#define H_DIM 512
#define B_DIM 8
#define HW (H_DIM * W_DIM)
#define NPIX (B_DIM * HW)

// fp16 repacked images: (B,H,W,4) half, 8 bytes/pixel, 16.78MB each.
__device__ __align__(16) __half g_half[2][(size_t)NPIX * 4];

// ---------------- pre-pass: fp32 RGB -> half RGBx ----------------
__global__ void __launch_bounds__(256)
convert_kernel(const float* __restrict__ I0, const float* __restrict__ I1) {
    int img = blockIdx.y;
    const float* src = img ? I1 : I0;
    int tid = blockIdx.x * blockDim.x + threadIdx.x;   // one thread = 4 pixels
    if (tid >= NPIX / 4) return;

    const float4* s4 = (const float4*)src + (size_t)tid * 3;  // 12 floats
    float4 A = __ldg(s4 + 0);
    float4 B = __ldg(s4 + 1);
    float4 C = __ldg(s4 + 2);

    union { __half2 h[8]; float4 v[2]; } o;
    // px0: A.x A.y A.z | px1: A.w B.x B.y | px2: B.z B.w C.x | px3: C.y C.z C.w
    o.h[0] = __floats2half2_rn(A.x, A.y);
    o.h[1] = __floats2half2_rn(A.z, 0.f);
    o.h[2] = __floats2half2_rn(A.w, B.x);
    o.h[3] = __floats2half2_rn(B.y, 0.f);
    o.h[4] = __floats2half2_rn(B.z, B.w);
    o.h[5] = __floats2half2_rn(C.x, 0.f);
    o.h[6] = __floats2half2_rn(C.y, C.z);
    o.h[7] = __floats2half2_rn(C.w, 0.f);

    float4* dst = (float4*)(&g_half[img][(size_t)tid * 16]);
    dst[0] = o.v[0];
    dst[1] = o.v[1];
}

// ---------------- main kernel ----------------
__device__ __forceinline__ float3 bilerp3h(const __half* __restrict__ img,
                                           float x, float y) {
    float x0f = floorf(x);
    float y0f = floorf(y);
    float wx = x - x0f;
    float wy = y - y0f;
    int x0 = min(max((int)x0f, 0), W_DIM - 1);
    int x1 = min(max((int)x0f + 1, 0), W_DIM - 1);
    int y0 = min(max((int)y0f, 0), H_DIM - 1);
    int y1 = min(max((int)y0f + 1, 0), H_DIM - 1);

    float wa = (1.f - wx) * (1.f - wy);
    float wb = (1.f - wx) * wy;
    float wc = wx * (1.f - wy);
    float wd = wx * wy;

    const __half* r0 = img + y0 * (W_DIM * 4);
    const __half* r1 = img + y1 * (W_DIM * 4);

    // 4 corners, one LDG.64 each (8B aligned: offsets are multiples of 8B)
    uint2 qa = __ldg((const uint2*)(r0 + x0 * 4));
    uint2 qb = __ldg((const uint2*)(r1 + x0 * 4));
    uint2 qc = __ldg((const uint2*)(r0 + x1 * 4));
    uint2 qd = __ldg((const uint2*)(r1 + x1 * 4));

    float2 a01 = __half22float2(*(__half2*)&qa.x);
    float2 a2_ = __half22float2(*(__half2*)&qa.y);
    float2 b01 = __half22float2(*(__half2*)&qb.x);
    float2 b2_ = __half22float2(*(__half2*)&qb.y);
    float2 c01 = __half22float2(*(__half2*)&qc.x);
    float2 c2_ = __half22float2(*(__half2*)&qc.y);
    float2 d01 = __half22float2(*(__half2*)&qd.x);
    float2 d2_ = __half22float2(*(__half2*)&qd.y);

    float3 o;
    o.x = a01.x * wa + b01.x * wb + c01.x * wc + d01.x * wd;
    o.y = a01.y * wa + b01.y * wb + c01.y * wc + d01.y * wd;
    o.z = a2_.x * wa + b2_.x * wb + c2_.x * wc + d2_.x * wd;
    return o;
}

__global__ void __launch_bounds__(256)
imagecomp_kernel(const float* __restrict__ t,
                 const float* __restrict__ interp,
                 const float* __restrict__ F0,
                 const float* __restrict__ F1,
                 float* __restrict__ out) {
    int idx = blockIdx.x * blockDim.x + threadIdx.x;
    if (idx >= NPIX) return;

    int b = idx >> 18;
    int p = idx & (HW - 1);
    int yi = p >> 9;
    int xi = p & (W_DIM - 1);

    const float* ip = interp + (size_t)idx * 5;
    float c0 = __ldg(ip + 0);
    float c1 = __ldg(ip + 1);
    float c2 = __ldg(ip + 2);
    float c3 = __ldg(ip + 3);
    float c4 = __ldg(ip + 4);

    float2 f0 = __ldg((const float2*)F0 + idx);
    float2 f1 = __ldg((const float2*)F1 + idx);

    float ft0x = c0 + f0.x, ft0y = c1 + f0.y;
    float ft1x = c2 + f1.x, ft1y = c3 + f1.y;

    float vt0 = 1.f / (1.f + __expf(-c4));
    float vt1 = 1.f - vt0;

    float tb = __ldg(t + b);
    float w0 = (1.f - tb) * vt0;
    float w1 = tb * vt1;
    float inv_den = __fdividef(1.f, w0 + w1 + 1e-12f);

    const __half* img0 = &g_half[0][(size_t)b * (HW * 4)];
    const __half* img1 = &g_half[1][(size_t)b * (HW * 4)];

    float gx = (float)xi, gy = (float)yi;
    float3 g0 = bilerp3h(img0, gx + ft0x, gy + ft0y);
    float3 g1 = bilerp3h(img1, gx + ft1x, gy + ft1y);

    float* o = out + (size_t)idx * 3;
    o[0] = (w0 * g0.x + w1 * g1.x) * inv_den;
    o[1] = (w0 * g0.y + w1 * g1.y) * inv_den;
    o[2] = (w0 * g0.z + w1 * g1.z) * inv_den;
}

extern "C" void kernel_launch(void* const* d_in, const int* in_sizes, int n_in,
                              void* d_out, int out_size) {
    const float* t      = (const float*)d_in[0];
    const float* I0     = (const float*)d_in[1];
    const float* I1     = (const float*)d_in[2];
    const float* interp = (const float*)d_in[3];
    const float* F0     = (const float*)d_in[4];
    const float* F1     = (const float*)d_in[5];
    float* out = (float*)d_out;

    int threads = 256;
    dim3 cgrid((NPIX / 4 + threads - 1) / threads, 2);
    convert_kernel<<<cgrid, threads>>>(I0, I1);

    int blocks = (NPIX + threads - 1) / threads;
    imagecomp_kernel<<<blocks, threads>>>(t, interp, F0, F1, out);
}